// round 11
// baseline (speedup 1.0000x reference)
#include <cuda_runtime.h>
#include <cstdint>
#include <math.h>

// NT_Xent collapsed: neg_n = (r_n/||r_n||) . S / T,  S = sum_m mem_m/||mem_m||.
// One persistent kernel, grid = 148 x 512 (1 block/SM, all co-resident).
// Phase 1: R1's measured-best shape (512 thr, strided warp rows) widened to
//          8 rows in flight per warp (needs >64 regs -> no min-blocks clause).
// pos-part of the loss (independent of S) is computed BEFORE the grid sync to
// overlap with straggler blocks; only rs = r^.S happens after.
// grid-sync; Phase 2: rebuild S in parallel, finish loss, last block -> mean.
// All reductions are fixed-order trees -> deterministic.

#define D      128
#define DV     32             // float4 per row
#define GRID   148
#define T      512
#define NW     16             // warps per block
#define INV_T  10.0f
#define EPSN   1e-8f
#define EPS2   (1e-8f * 1e-8f)

__device__ float        g_partialS[GRID * D];
__device__ float        g_partialLoss[GRID];
__device__ unsigned int g_cnt1 = 0;
__device__ unsigned int g_cnt2 = 0;

__device__ __forceinline__ float warp_sum(float v) {
    #pragma unroll
    for (int o = 16; o > 0; o >>= 1) v += __shfl_xor_sync(0xffffffffu, v, o);
    return v;
}
__device__ __forceinline__ float dot4(float4 a, float4 b) {
    return a.x * b.x + a.y * b.y + a.z * b.z + a.w * b.w;
}

__global__ __launch_bounds__(T)   // no min-blocks clause: full reg budget
void fused_ntxent_kernel(const float4* __restrict__ mem, int M,
                         const float4* __restrict__ real,
                         const float4* __restrict__ pert, int N,
                         float* __restrict__ out) {
    __shared__ float4 sacc[NW][32];      // 8KB
    __shared__ float  Sq[4][D];          // 2KB
    __shared__ float  S[D];
    __shared__ float  wsum[NW];
    __shared__ int    islast;

    const int tid  = threadIdx.x;
    const int w    = tid >> 5;
    const int lane = tid & 31;
    const int bid  = blockIdx.x;
    const int gw   = bid * NW + w;       // global warp id
    const int W    = GRID * NW;          // 2368 warps

    // ================= Phase 1: strided rows, 8 in flight =================
    const int full = M / W;              // 27
    const int rem  = M - full * W;       // 1600
    const float4* base = mem + (size_t)gw * DV + lane;
    const size_t  step = (size_t)W * DV;

    float4 acc = make_float4(0.f, 0.f, 0.f, 0.f);

    int k = 0;
    #pragma unroll 1
    for (; k + 8 <= full; k += 8) {
        float4 v[8];
        #pragma unroll
        for (int u = 0; u < 8; u++) v[u] = base[(size_t)(k + u) * step];
        float s[8];
        #pragma unroll
        for (int u = 0; u < 8; u++) s[u] = dot4(v[u], v[u]);
        #pragma unroll
        for (int o = 16; o > 0; o >>= 1) {
            #pragma unroll
            for (int u = 0; u < 8; u++)
                s[u] += __shfl_xor_sync(0xffffffffu, s[u], o);
        }
        #pragma unroll
        for (int u = 0; u < 8; u++) {
            float inv = rsqrtf(fmaxf(s[u], EPS2));   // == 1/max(sqrt(s),EPS)
            acc.x += v[u].x * inv;  acc.y += v[u].y * inv;
            acc.z += v[u].z * inv;  acc.w += v[u].w * inv;
        }
    }
    // leftover rows (full%8 == 3) + remainder row, scalar
    #pragma unroll 1
    for (; k <= full; k++) {
        if (k == full && gw >= rem) break;
        float4 v = base[(size_t)k * step];
        float  s = warp_sum(dot4(v, v));
        float inv = rsqrtf(fmaxf(s, EPS2));
        acc.x += v.x * inv;  acc.y += v.y * inv;
        acc.z += v.z * inv;  acc.w += v.w * inv;
    }

    sacc[w][lane] = acc;
    __syncthreads();
    if (tid < D) {
        float s = 0.f;
        #pragma unroll
        for (int ww = 0; ww < NW; ww++)
            s += ((const float*)sacc[ww])[tid];
        g_partialS[bid * D + tid] = s;
    }
    __threadfence();
    __syncthreads();
    if (tid == 0) atomicAdd(&g_cnt1, 1u);

    // ===== pos-part of the loss: independent of S, overlap with stragglers =====
    const int n = w * GRID + bid;        // each n in [0,N) exactly once (N=1024)
    float4 rv = make_float4(0.f, 0.f, 0.f, 0.f);
    float  pos = 0.f, rn = 1.f;
    if (n < N) {
        rv = real[(size_t)n * DV + lane];
        float4 pv = pert[(size_t)n * DV + lane];
        float rr = warp_sum(dot4(rv, rv));
        float pp = warp_sum(dot4(rv, pv) * 0.f + dot4(pv, pv));  // pp
        float rp = warp_sum(dot4(rv, pv));
        rn = fmaxf(sqrtf(rr), EPSN);
        float pn = fmaxf(sqrtf(pp), EPSN);
        pos = rp / (rn * pn) * INV_T;
    }

    // ================= grid sync =================
    if (tid == 0) {
        while (*((volatile unsigned int*)&g_cnt1) != GRID) { }
        __threadfence();
    }
    __syncthreads();

    // ================= Phase 2a: rebuild S (parallel, fixed order) =================
    {
        const int col = tid & (D - 1);
        const int q   = tid >> 7;            // 0..3
        float s = 0.f;
        #pragma unroll 4
        for (int b = q; b < GRID; b += 4)
            s += g_partialS[b * D + col];
        Sq[q][col] = s;
    }
    __syncthreads();
    if (tid < D) {
        float t = 0.f;
        #pragma unroll
        for (int j = 0; j < 4; j++) t += Sq[j][tid];
        S[tid] = t;
    }
    __syncthreads();

    const float4 s4 = ((const float4*)S)[lane];

    // ================= Phase 2b: finish loss (needs S) =================
    float lsum = 0.f;
    if (n < N) {
        float rs = warp_sum(dot4(rv, s4));
        if (lane == 0) {
            float neg = rs / rn * INV_T;
            float mx  = fmaxf(pos, neg);
            float lse = mx + logf(expf(pos - mx) + expf(neg - mx));
            lsum = lse - pos;                // -log_softmax[0]
        }
    }
    if (lane == 0) wsum[w] = lsum;
    __syncthreads();

    if (tid == 0) {
        float b = 0.f;
        #pragma unroll
        for (int ww = 0; ww < NW; ww++) b += wsum[ww];
        g_partialLoss[bid] = b;
        __threadfence();
        unsigned int ret = atomicAdd(&g_cnt2, 1u);
        islast = (ret == GRID - 1) ? 1 : 0;
    }
    __syncthreads();

    if (islast && w == 0) {
        __threadfence();
        float v = 0.f;
        #pragma unroll
        for (int j = 0; j < 5; j++) {
            int i = lane + 32 * j;
            if (i < GRID) v += g_partialLoss[i];
        }
        v = warp_sum(v);
        if (lane == 0) {
            out[0] = v / (float)N;
            g_cnt1 = 0;
            g_cnt2 = 0;
        }
    }
}

extern "C" void kernel_launch(void* const* d_in, const int* in_sizes, int n_in,
                              void* d_out, int out_size) {
    const float4* real = (const float4*)d_in[0];
    const float4* pert = (const float4*)d_in[1];
    const float4* mem  = (const float4*)d_in[2];
    int N = in_sizes[0] / D;
    int M = in_sizes[2] / D;

    fused_ntxent_kernel<<<GRID, T>>>(mem, M, real, pert, N, (float*)d_out);
}

// round 12
// speedup vs baseline: 1.1009x; 1.1009x over previous
#include <cuda_runtime.h>
#include <cstdint>
#include <math.h>

// NT_Xent collapsed: neg_n = (r_n/||r_n||) . S / T,  S = sum_m mem_m/||mem_m||.
// One persistent kernel, grid = 148 x 544 (1 block/SM, all co-resident).
// Phase 1: warp-specialized TMA pipeline with BIG tiles: 6-stage ring of
//   32KB tiles (64 rows). One producer thread issues cp.async.bulk per tile
//   (overhead amortized 4x vs R9's 16KB tiles); 16 consumer warps each
//   normalize 4 rows/tile from smem. M divides exactly -> no tail path.
// pos-part of loss precomputed before grid-sync (independent of S).
// grid-sync; Phase 2: rebuild S in parallel, finish loss, last block -> mean.
// All reductions are fixed-order trees -> deterministic.

#define D        128
#define DV       32                 // float4 per row
#define GRID     148
#define NW_C     16                 // consumer warps
#define T        ((NW_C + 1) * 32)  // 544
#define TILE_R   64                 // rows per tile
#define TILE_V4  (TILE_R * DV)      // 2048 float4
#define TILE_B   (TILE_V4 * 16)     // 32768 bytes
#define NSTAGE   6
#define SMEM_DYN (NSTAGE * TILE_B)  // 196608
#define INV_T    10.0f
#define EPSN     1e-8f
#define EPS2     (1e-8f * 1e-8f)

__device__ float        g_partialS[GRID * D];
__device__ float        g_partialLoss[GRID];
__device__ unsigned int g_cnt1 = 0;
__device__ unsigned int g_cnt2 = 0;

__device__ __forceinline__ float warp_sum(float v) {
    #pragma unroll
    for (int o = 16; o > 0; o >>= 1) v += __shfl_xor_sync(0xffffffffu, v, o);
    return v;
}
__device__ __forceinline__ float dot4(float4 a, float4 b) {
    return a.x * b.x + a.y * b.y + a.z * b.z + a.w * b.w;
}
__device__ __forceinline__ void mbar_init(unsigned int a, unsigned int cnt) {
    asm volatile("mbarrier.init.shared.b64 [%0], %1;" :: "r"(a), "r"(cnt) : "memory");
}
__device__ __forceinline__ void mbar_arrive(unsigned int a) {
    asm volatile("mbarrier.arrive.shared.b64 _, [%0];" :: "r"(a) : "memory");
}
__device__ __forceinline__ void mbar_expect_tx(unsigned int a, unsigned int tx) {
    asm volatile("mbarrier.arrive.expect_tx.shared.b64 _, [%0], %1;"
                 :: "r"(a), "r"(tx) : "memory");
}
__device__ __forceinline__ void mbar_wait(unsigned int a, unsigned int parity) {
    asm volatile(
        "{\n\t"
        ".reg .pred P;\n\t"
        "WAIT_%=:\n\t"
        "mbarrier.try_wait.parity.acquire.cta.shared::cta.b64 P, [%0], %1, 0x989680;\n\t"
        "@P bra DONE_%=;\n\t"
        "bra WAIT_%=;\n\t"
        "DONE_%=:\n\t"
        "}" :: "r"(a), "r"(parity) : "memory");
}
__device__ __forceinline__ void tma_bulk_1d(unsigned int dst, const void* src,
                                            unsigned int bytes, unsigned int mbar) {
    asm volatile(
        "cp.async.bulk.shared::cta.global.mbarrier::complete_tx::bytes [%0], [%1], %2, [%3];"
        :: "r"(dst), "l"(src), "r"(bytes), "r"(mbar) : "memory");
}

__global__ __launch_bounds__(T, 1)
void fused_ntxent_kernel(const float4* __restrict__ mem, int M,
                         const float4* __restrict__ real,
                         const float4* __restrict__ pert, int N,
                         float* __restrict__ out) {
    extern __shared__ float4 stages[];            // 192KB ring

    __shared__ unsigned long long mbar_full[NSTAGE];
    __shared__ unsigned long long mbar_empty[NSTAGE];
    __shared__ float4 sacc[NW_C][32];             // 8KB
    __shared__ float  Sq[4][D];                   // 2KB
    __shared__ float  S[D];
    __shared__ float  wsum[NW_C + 1];
    __shared__ int    islast;

    const int tid  = threadIdx.x;
    const int w    = tid >> 5;
    const int lane = tid & 31;
    const int bid  = blockIdx.x;

    const unsigned int ring  = (unsigned int)__cvta_generic_to_shared(stages);
    const unsigned int fullb = (unsigned int)__cvta_generic_to_shared(mbar_full);
    const unsigned int emptb = (unsigned int)__cvta_generic_to_shared(mbar_empty);

    if (tid == 0) {
        #pragma unroll
        for (int s = 0; s < NSTAGE; s++) {
            mbar_init(fullb + 8u * s, 1);        // producer expect_tx + tx bytes
            mbar_init(emptb + 8u * s, NW_C);     // one arrive per consumer warp
        }
        asm volatile("fence.proxy.async.shared::cta;" ::: "memory");
    }
    __syncthreads();

    // ================= Phase 1: TMA-fed pipeline, 32KB tiles =================
    const int NTILES = M / TILE_R;                         // 1024 (exact)
    const int cnt    = (NTILES - bid + GRID - 1) / GRID;   // tiles for this block

    float4 acc = make_float4(0.f, 0.f, 0.f, 0.f);

    if (w == NW_C) {
        // -------- producer (lane 0) --------
        if (lane == 0) {
            int stage = 0, phase = 1;            // first NSTAGE empty-waits pass
            #pragma unroll 1
            for (int k = 0; k < cnt; k++) {
                mbar_wait(emptb + 8u * stage, phase);
                mbar_expect_tx(fullb + 8u * stage, TILE_B);
                tma_bulk_1d(ring + (unsigned int)stage * TILE_B,
                            mem + (size_t)(bid + (size_t)k * GRID) * TILE_V4,
                            TILE_B, fullb + 8u * stage);
                if (++stage == NSTAGE) { stage = 0; phase ^= 1; }
            }
        }
    } else {
        // -------- consumers: rows 4w..4w+3 of each tile --------
        int stage = 0, phase = 0;
        #pragma unroll 1
        for (int k = 0; k < cnt; k++) {
            mbar_wait(fullb + 8u * stage, phase);
            const float4* tile = stages + stage * TILE_V4;
            float4 v[4];
            #pragma unroll
            for (int j = 0; j < 4; j++)
                v[j] = tile[(4 * w + j) * DV + lane];
            float s[4];
            #pragma unroll
            for (int j = 0; j < 4; j++) s[j] = dot4(v[j], v[j]);
            #pragma unroll
            for (int o = 16; o > 0; o >>= 1) {
                #pragma unroll
                for (int j = 0; j < 4; j++)
                    s[j] += __shfl_xor_sync(0xffffffffu, s[j], o);
            }
            #pragma unroll
            for (int j = 0; j < 4; j++) {
                float inv = rsqrtf(fmaxf(s[j], EPS2));  // == 1/max(sqrt,EPS)
                acc.x += v[j].x * inv;  acc.y += v[j].y * inv;
                acc.z += v[j].z * inv;  acc.w += v[j].w * inv;
            }
            __syncwarp();
            if (lane == 0) mbar_arrive(emptb + 8u * stage);
            if (++stage == NSTAGE) { stage = 0; phase ^= 1; }
        }
        sacc[w][lane] = acc;
    }
    __syncthreads();

    if (tid < D) {
        float s = 0.f;
        #pragma unroll
        for (int ww = 0; ww < NW_C; ww++)
            s += ((const float*)sacc[ww])[tid];
        g_partialS[bid * D + tid] = s;
    }
    __threadfence();
    __syncthreads();
    if (tid == 0) atomicAdd(&g_cnt1, 1u);

    // ===== pos-part of the loss (independent of S): overlap with stragglers =====
    const int n = w * GRID + bid;                // 17*148=2516 >= N, each n once
    float4 rv = make_float4(0.f, 0.f, 0.f, 0.f);
    float  pos = 0.f, rn = 1.f;
    if (n < N) {
        rv = real[(size_t)n * DV + lane];
        float4 pv = pert[(size_t)n * DV + lane];
        float rr = warp_sum(dot4(rv, rv));
        float pp = warp_sum(dot4(pv, pv));
        float rp = warp_sum(dot4(rv, pv));
        rn = fmaxf(sqrtf(rr), EPSN);
        float pn = fmaxf(sqrtf(pp), EPSN);
        pos = rp / (rn * pn) * INV_T;
    }

    // ================= grid sync =================
    if (tid == 0) {
        while (*((volatile unsigned int*)&g_cnt1) != GRID) { }
        __threadfence();
    }
    __syncthreads();

    // ================= Phase 2a: rebuild S (parallel, fixed order) =================
    if (tid < 512) {
        const int col = tid & (D - 1);
        const int q   = tid >> 7;                // 0..3
        float s = 0.f;
        #pragma unroll 4
        for (int b = q; b < GRID; b += 4)
            s += g_partialS[b * D + col];
        Sq[q][col] = s;
    }
    __syncthreads();
    if (tid < D) {
        float t = 0.f;
        #pragma unroll
        for (int j = 0; j < 4; j++) t += Sq[j][tid];
        S[tid] = t;
    }
    __syncthreads();

    const float4 s4 = ((const float4*)S)[lane];

    // ================= Phase 2b: finish loss (needs S) =================
    float lsum = 0.f;
    if (n < N) {
        float rs = warp_sum(dot4(rv, s4));
        if (lane == 0) {
            float neg = rs / rn * INV_T;
            float mx  = fmaxf(pos, neg);
            float lse = mx + logf(expf(pos - mx) + expf(neg - mx));
            lsum = lse - pos;                    // -log_softmax[0]
        }
    }
    if (lane == 0) wsum[w] = lsum;
    __syncthreads();

    if (tid == 0) {
        float b = 0.f;
        #pragma unroll
        for (int ww = 0; ww <= NW_C; ww++) b += wsum[ww];
        g_partialLoss[bid] = b;
        __threadfence();
        unsigned int ret = atomicAdd(&g_cnt2, 1u);
        islast = (ret == GRID - 1) ? 1 : 0;
    }
    __syncthreads();

    if (islast && w == 0) {
        __threadfence();
        float v = 0.f;
        #pragma unroll
        for (int j = 0; j < 5; j++) {
            int i = lane + 32 * j;
            if (i < GRID) v += g_partialLoss[i];
        }
        v = warp_sum(v);
        if (lane == 0) {
            out[0] = v / (float)N;
            g_cnt1 = 0;
            g_cnt2 = 0;
        }
    }
}

extern "C" void kernel_launch(void* const* d_in, const int* in_sizes, int n_in,
                              void* d_out, int out_size) {
    const float4* real = (const float4*)d_in[0];
    const float4* pert = (const float4*)d_in[1];
    const float4* mem  = (const float4*)d_in[2];
    int N = in_sizes[0] / D;
    int M = in_sizes[2] / D;

    // Opt in to large dynamic smem. No graph node, no allocation, idempotent.
    cudaFuncSetAttribute(fused_ntxent_kernel,
                         cudaFuncAttributeMaxDynamicSharedMemorySize, SMEM_DYN);

    fused_ntxent_kernel<<<GRID, T, SMEM_DYN>>>(mem, M, real, pert, N,
                                               (float*)d_out);
}